// round 15
// baseline (speedup 1.0000x reference)
#include <cuda_runtime.h>
#include <cuda_fp16.h>
#include <cuda_fp8.h>
#include <mma.h>

using namespace nvcuda;

#define GN 3
constexpr int NN = 16512;     // K + EXER entities  (= 129 * 128 exactly)
constexpr int KD = 128;       // embedding dim
constexpr int EE = 400000;    // edges per graph (divisible by 16)
constexpr int BB = 4096;      // batch
constexpr int TT = 204800;    // history length
constexpr int H1 = 512;
constexpr int H2 = 216;
constexpr int H2P = 224;      // padded to 14*16
constexpr int CSRN = 680000;  // per-graph CSR capacity (rows padded to mult of 16)
constexpr int AP2 = 40;       // A-tile smem row pitch (halves), BK=32

// block partitioning of the fused setup kernel
constexpr int DEG_B  = (GN * (EE / 8) + 255) / 256;            // 586
constexpr int INIT_B = (NN * KD / 4) / 256;                    // 2064
constexpr int WCONV_N = GN * 4 * KD * KD + KD * H1 + H1 * H2P + 4 * KD;
constexpr int WCONV_B = (WCONV_N + 255) / 256;                 // 1474
constexpr int SEG_B  = (BB + 1 + 255) / 256;                   // 17
// mlp2 fused tail: 64 gemm CTAs + deg-zero CTAs (128 threads each)
constexpr int MLP2_B = BB / 64;                                // 64
constexpr int ZERO_B = (2 * GN * NN + 127) / 128;              // 775

// ---------------- scratch (static device globals; no allocation) ----------------
__device__ int            d_deg_s[GN][NN];
__device__ int            d_deg_d[GN][NN];
__device__ int            d_rowp[GN][NN];    // 16-aligned row starts
__device__ int            d_rowe[GN][NN];    // true row ends (start + degree)
__device__ int            d_cur[GN][NN];
__device__ unsigned       d_csr4[GN][CSRN];  // src:16 | fp16 rsqrt(deg_s[src]):16 ; pad=0
__device__ unsigned char  d_h8a[NN * KD];    // fp8 e4m3 activations (gather source)
__device__ unsigned char  d_h8b[NN * KD];
__device__ __half         d_aggh[GN][NN * KD];   // fp16 aggregation (A for tensor GEMM)
__device__ __half         d_Wh[GN * 4 * KD * KD];// fp16 GCN weights [g][l][k][n]
__device__ float          d_biasC[4][KD];        // per-layer combined bias (sum over g)
__device__ __half         d_W1h[KD * H1];
__device__ __half         d_W2h[H1 * H2P];       // zero-padded cols
__device__ float          d_sumA[NN * KD];  // entity_emb + h1+h2+h3+h4  (full = /5)
__device__ float          d_sumL[NN * KD];  // h3 (partial)
__device__ __half         d_sumLh[NN * KD]; // h3 + h4 fp16 (disc_full*2) for head2
__device__ int            d_segs[BB + 1];
__device__ float          d_cvec[2 * KD];
__device__ __half         d_xh[BB * KD];
__device__ __half         d_x1h[BB * H1];

__device__ __forceinline__ float sigm(float x) { return 1.f / (1.f + __expf(-x)); }

// ------- fused setup: degree atomics | init | weight conv | segstart ----------
__global__ void k_setup(const int* __restrict__ s0, const int* __restrict__ d0,
                        const int* __restrict__ s1, const int* __restrict__ d1,
                        const int* __restrict__ s2, const int* __restrict__ d2,
                        const float* __restrict__ ent,
                        const float* __restrict__ gcnW, const float* __restrict__ gcnB,
                        const float* __restrict__ W1, const float* __restrict__ W2,
                        const int* __restrict__ hseg) {
    int b = blockIdx.x, tid = threadIdx.x;
    if (b < DEG_B) {
        int i = b * 256 + tid;
        const int Q = EE / 8;
        if (i >= GN * Q) return;
        int g = i / Q, e8 = (i - g * Q) * 8;
        const int* S = (g == 0) ? s0 : (g == 1) ? s1 : s2;
        const int* D = (g == 0) ? d0 : (g == 1) ? d1 : d2;
        int4 sa = *(const int4*)&S[e8];
        int4 sb = *(const int4*)&S[e8 + 4];
        int4 da = *(const int4*)&D[e8];
        int4 db = *(const int4*)&D[e8 + 4];
        atomicAdd(&d_deg_s[g][sa.x], 1); atomicAdd(&d_deg_s[g][sa.y], 1);
        atomicAdd(&d_deg_s[g][sa.z], 1); atomicAdd(&d_deg_s[g][sa.w], 1);
        atomicAdd(&d_deg_s[g][sb.x], 1); atomicAdd(&d_deg_s[g][sb.y], 1);
        atomicAdd(&d_deg_s[g][sb.z], 1); atomicAdd(&d_deg_s[g][sb.w], 1);
        atomicAdd(&d_deg_d[g][da.x], 1); atomicAdd(&d_deg_d[g][da.y], 1);
        atomicAdd(&d_deg_d[g][da.z], 1); atomicAdd(&d_deg_d[g][da.w], 1);
        atomicAdd(&d_deg_d[g][db.x], 1); atomicAdd(&d_deg_d[g][db.y], 1);
        atomicAdd(&d_deg_d[g][db.z], 1); atomicAdd(&d_deg_d[g][db.w], 1);
    } else if (b < DEG_B + INIT_B) {
        int i = (b - DEG_B) * 256 + tid;
        float4 v = ((const float4*)ent)[i];
        ((float4*)d_sumA)[i] = v;
        ((float4*)d_sumL)[i] = make_float4(0.f, 0.f, 0.f, 0.f);
        __nv_fp8x2_storage_t lo =
            __nv_cvt_float2_to_fp8x2(make_float2(v.x, v.y), __NV_SATFINITE, __NV_E4M3);
        __nv_fp8x2_storage_t hi =
            __nv_cvt_float2_to_fp8x2(make_float2(v.z, v.w), __NV_SATFINITE, __NV_E4M3);
        ((unsigned*)d_h8a)[i] = (unsigned)lo | ((unsigned)hi << 16);
    } else if (b < DEG_B + INIT_B + WCONV_B) {
        int i = (b - DEG_B - INIT_B) * 256 + tid;
        const int A = GN * 4 * KD * KD;
        const int B = A + KD * H1;
        const int C = B + H1 * H2P;
        const int D = C + 4 * KD;
        if (i < A) {
            d_Wh[i] = __float2half_rn(gcnW[i]);
        } else if (i < B) {
            int j = i - A;
            d_W1h[j] = __float2half_rn(W1[j]);
        } else if (i < C) {
            int j = i - B;
            int k = j / H2P, n = j - k * H2P;
            d_W2h[j] = __float2half_rn(n < H2 ? W2[k * H2 + n] : 0.f);
        } else if (i < D) {
            int j = i - C;
            int l = j >> 7, col = j & 127;
            d_biasC[l][col] = gcnB[l * KD + col] + gcnB[4 * KD + l * KD + col]
                            + gcnB[8 * KD + l * KD + col];
        }
    } else {
        int i = (b - DEG_B - INIT_B - WCONV_B) * 256 + tid;
        if (i > BB) return;
        int lo = 0, hi = TT;
        while (lo < hi) { int m = (lo + hi) >> 1; if (hseg[m] < i) lo = m + 1; else hi = m; }
        d_segs[i] = lo;
    }
}

// exclusive scan of 16-ALIGNED in-degree -> row starts + true ends.
__global__ void k_scan() {
    __shared__ int sA[1024], sB[1024];
    int g = blockIdx.x, t = threadIdx.x;
    const int CH = (NN + 1023) / 1024;   // 17
    int base = t * CH;
    int s = 0;
    for (int i = 0; i < CH; i++) {
        int idx = base + i;
        if (idx < NN) s += (d_deg_d[g][idx] + 15) & ~15;
    }
    sA[t] = s;
    __syncthreads();
    int* a = sA; int* b = sB;
    for (int off = 1; off < 1024; off <<= 1) {
        b[t] = a[t] + ((t >= off) ? a[t - off] : 0);
        __syncthreads();
        int* tmp = a; a = b; b = tmp;
    }
    int incl = a[t];
    int run = incl - s;
    for (int i = 0; i < CH; i++) {
        int idx = base + i;
        if (idx < NN) {
            int deg = d_deg_d[g][idx];
            d_rowp[g][idx] = run;
            d_rowe[g][idx] = run + deg;
            d_cur[g][idx] = run;
            run += (deg + 15) & ~15;
        }
    }
}

// 16 edges per thread: deg_s gather + atomic cursor + 4-byte scatter
__global__ void k_fill(const int* __restrict__ s0, const int* __restrict__ d0,
                       const int* __restrict__ s1, const int* __restrict__ d1,
                       const int* __restrict__ s2, const int* __restrict__ d2) {
    int i = blockIdx.x * blockDim.x + threadIdx.x;
    const int Q = EE / 16;
    if (i >= GN * Q) return;
    int g = i / Q, e16 = (i - g * Q) * 16;
    const int* S = (g == 0) ? s0 : (g == 1) ? s1 : s2;
    const int* D = (g == 0) ? d0 : (g == 1) ? d1 : d2;
    int sv[16], dv[16];
#pragma unroll
    for (int q = 0; q < 4; q++) {
        *(int4*)&sv[q * 4] = *(const int4*)&S[e16 + q * 4];
        *(int4*)&dv[q * 4] = *(const int4*)&D[e16 + q * 4];
    }
    int ds[16];
#pragma unroll
    for (int q = 0; q < 16; q++) ds[q] = d_deg_s[g][sv[q]];
    int pos[16];
#pragma unroll
    for (int q = 0; q < 16; q++) pos[q] = atomicAdd(&d_cur[g][dv[q]], 1);
#pragma unroll
    for (int q = 0; q < 16; q++) {
        unsigned hb = (unsigned)__half_as_ushort(
            __float2half_rn(rsqrtf((float)max(ds[q], 1))));
        d_csr4[g][pos[q]] = (unsigned)sv[q] | (hb << 16);
    }
}

// ---------------- GCN aggregation: persistent warps over (g, dst-row) ---------
constexpr int AGG_CTAS = 1184;   // 148 SM x 8 CTAs — one wave
__global__ void __launch_bounds__(256) k_agg(int layer) {
    int tw = (blockIdx.x * 256 + threadIdx.x) >> 5;
    int lane = threadIdx.x & 31;
    const int nwarps = AGG_CTAS * 8;
    const unsigned char* __restrict__ hin = (layer & 1) ? d_h8b : d_h8a;
    int grp = lane >> 3, sub = lane & 7;

    for (int w = tw; w < GN * NN; w += nwarps) {
        int g = w / NN, n = w - g * NN;
        int e0 = d_rowp[g][n], ee = d_rowe[g][n];
        int deg = ee - e0;
        int e1a = e0 + ((deg + 15) & ~15);
        const unsigned* __restrict__ cs = d_csr4[g];
        const unsigned char* __restrict__ hcol = hin + sub * 16;
        __half2 acc[8];
#pragma unroll
        for (int j = 0; j < 8; j++) acc[j] = __floats2half2_rn(0.f, 0.f);

        for (int base = e0; base < e1a; base += 16) {
            uint4 rr = *(const uint4*)&cs[base + 4 * grp];
            unsigned r[4] = {rr.x, rr.y, rr.z, rr.w};
            uint4 v[4];
#pragma unroll
            for (int q = 0; q < 4; q++)
                v[q] = *(const uint4*)(hcol + (int)(r[q] & 0xFFFFu) * KD);
#pragma unroll
            for (int q = 0; q < 4; q++) {
                unsigned wd = __byte_perm(r[q], r[q], 0x3232);  // {w,w} fp16x2
                __half2 w2 = *(__half2*)&wd;
                const unsigned* p = &v[q].x;
#pragma unroll
                for (int t = 0; t < 4; t++) {
                    unsigned word = p[t];
                    __half2_raw hlo = __nv_cvt_fp8x2_to_halfraw2(
                        (__nv_fp8x2_storage_t)(word & 0xFFFFu), __NV_E4M3);
                    __half2_raw hhi = __nv_cvt_fp8x2_to_halfraw2(
                        (__nv_fp8x2_storage_t)(word >> 16), __NV_E4M3);
                    acc[2 * t]     = __hfma2(w2, *(__half2*)&hlo, acc[2 * t]);
                    acc[2 * t + 1] = __hfma2(w2, *(__half2*)&hhi, acc[2 * t + 1]);
                }
            }
        }
#pragma unroll
        for (int j = 0; j < 8; j++) {
            unsigned u = *(unsigned*)&acc[j];
            unsigned vv = __shfl_xor_sync(0xffffffffu, u, 8);
            __half2 t = __hadd2(acc[j], *(__half2*)&vv);
            unsigned u2 = *(unsigned*)&t;
            unsigned v2 = __shfl_xor_sync(0xffffffffu, u2, 16);
            acc[j] = __hadd2(t, *(__half2*)&v2);
        }
        if (grp == 0) {
            float rsd = rsqrtf((float)max(deg, 1));
            uint4 o0, o1;
            unsigned* oo = &o0.x;
#pragma unroll
            for (int j = 0; j < 8; j++) {
                float2 f = __half22float2(acc[j]);
                __half2 h = __floats2half2_rn(f.x * rsd, f.y * rsd);
                if (j == 4) oo = &o1.x;
                oo[j & 3] = *(unsigned*)&h;
            }
            __half* dst = &d_aggh[g][n * KD + sub * 16];
            *(uint4*)dst = o0;
            *(uint4*)(dst + 8) = o1;
        }
    }
}

// ---------------- GCN GEMM: 64-row tiles, 128 thr, BK=32, double-buffered -----
__global__ void __launch_bounds__(128) k_gemmT(int layer) {
    extern __shared__ char smem[];
    __half* Wb = (__half*)smem;                 // 2 x 4096 halves = 16384 B
    __half* Ab = (__half*)(smem + 16384);       // 2 x 64*AP2 halves = 10240 B
    float* stage = (float*)smem;                // 32 KB epilogue overlay
    int tid = threadIdx.x, w = tid >> 5, lane = tid & 31;
    int row0c = blockIdx.x * 64;
    int ar0 = tid >> 2, ac0 = (tid & 3) * 8;
    int ar1 = (tid + 128) >> 2;

    {   // kt = 0: g=0, ks=0
        const uint4* wsrc = (const uint4*)(d_Wh + (size_t)layer * 16384);
#pragma unroll
        for (int q = 0; q < 4; q++) ((uint4*)Wb)[tid + q * 128] = wsrc[tid + q * 128];
        *(uint4*)(Ab + ar0 * AP2 + ac0) =
            *(const uint4*)(d_aggh[0] + (row0c + ar0) * KD + ac0);
        *(uint4*)(Ab + ar1 * AP2 + ac0) =
            *(const uint4*)(d_aggh[0] + (row0c + ar1) * KD + ac0);
    }
    __syncthreads();

    wmma::fragment<wmma::accumulator, 16, 16, 16, float> c[8];
#pragma unroll
    for (int n = 0; n < 8; n++) wmma::fill_fragment(c[n], 0.f);

    for (int kt = 0; kt < 12; kt++) {
        int cur = kt & 1;
        uint4 wn[4], an0, an1;
        if (kt < 11) {
            int k1 = kt + 1, g1 = k1 >> 2, ks1 = (k1 & 3) * 32;
            const uint4* wsrc = (const uint4*)(d_Wh + (size_t)(g1 * 4 + layer) * 16384
                                               + ks1 * 128);
#pragma unroll
            for (int q = 0; q < 4; q++) wn[q] = wsrc[tid + q * 128];
            an0 = *(const uint4*)(d_aggh[g1] + (row0c + ar0) * KD + ks1 + ac0);
            an1 = *(const uint4*)(d_aggh[g1] + (row0c + ar1) * KD + ks1 + ac0);
        }
#pragma unroll
        for (int kk = 0; kk < 2; kk++) {
            wmma::fragment<wmma::matrix_a, 16, 16, 16, __half, wmma::row_major> a;
            wmma::load_matrix_sync(a, Ab + cur * 64 * AP2 + (w * 16) * AP2 + kk * 16, AP2);
#pragma unroll
            for (int n = 0; n < 8; n++) {
                wmma::fragment<wmma::matrix_b, 16, 16, 16, __half, wmma::row_major> b;
                wmma::load_matrix_sync(b, Wb + cur * 4096 + kk * 16 * 128 + n * 16, 128);
                wmma::mma_sync(c[n], a, b, c[n]);
            }
        }
        if (kt < 11) {
            int nb = cur ^ 1;
#pragma unroll
            for (int q = 0; q < 4; q++) ((uint4*)(Wb + nb * 4096))[tid + q * 128] = wn[q];
            *(uint4*)(Ab + nb * 64 * AP2 + ar0 * AP2 + ac0) = an0;
            *(uint4*)(Ab + nb * 64 * AP2 + ar1 * AP2 + ac0) = an1;
        }
        __syncthreads();
    }

    float* st = stage + w * 2048;
#pragma unroll
    for (int n = 0; n < 8; n++)
        wmma::store_matrix_sync(st + n * 16, c[n], 128, wmma::mem_row_major);
    __syncwarp();

    int col0 = lane * 4;
    float4 bias = *(const float4*)&d_biasC[layer][col0];
    unsigned char* hout = (layer & 1) ? d_h8a : d_h8b;
    int row0 = row0c + w * 16;
#pragma unroll
    for (int r = 0; r < 16; r++) {
        float4 v = *(float4*)&st[r * 128 + col0];
        v.x += bias.x; v.y += bias.y; v.z += bias.z; v.w += bias.w;
        int base = (row0 + r) * KD + col0;
        __nv_fp8x2_storage_t lo =
            __nv_cvt_float2_to_fp8x2(make_float2(v.x, v.y), __NV_SATFINITE, __NV_E4M3);
        __nv_fp8x2_storage_t hi =
            __nv_cvt_float2_to_fp8x2(make_float2(v.z, v.w), __NV_SATFINITE, __NV_E4M3);
        *(unsigned*)&hout[base] = (unsigned)lo | ((unsigned)hi << 16);
        float4 sa = *(float4*)&d_sumA[base];
        sa.x += v.x; sa.y += v.y; sa.z += v.z; sa.w += v.w;
        *(float4*)&d_sumA[base] = sa;
        if (layer == 2) {
            *(float4*)&d_sumL[base] = v;
        } else if (layer == 3) {
            float4 sl = *(float4*)&d_sumL[base];
            __half2 s01 = __floats2half2_rn(sl.x + v.x, sl.y + v.y);
            __half2 s23 = __floats2half2_rn(sl.z + v.z, sl.w + v.w);
            uint2 sv2;
            sv2.x = *(unsigned*)&s01;
            sv2.y = *(unsigned*)&s23;
            *(uint2*)&d_sumLh[base] = sv2;
        }
    }
}

// ---------------- head ----------------
// cvec: warp per dot product (256 warps)
__global__ void k_head1(const float* __restrict__ stuW, const float* __restrict__ exeW) {
    int wix = blockIdx.x * 8 + (threadIdx.x >> 5);
    int lanei = threadIdx.x & 31;
    int j = wix & 127;
    bool isE = wix >= 128;
    const float* wv = isE ? (exeW + KD) : (stuW + KD);
    float s = 0.f;
    for (int k = lanei; k < KD; k += 32) s += d_sumA[j * KD + k] * wv[k];
#pragma unroll
    for (int o = 16; o; o >>= 1) s += __shfl_xor_sync(0xffffffffu, s, o);
    if (lanei == 0) d_cvec[(isE ? KD : 0) + j] = s * 0.2f;
}

// fused stu-mean + x computation: warp per batch element
__global__ void k_head2(const int* __restrict__ hist,
                        const float* __restrict__ fsW, const float* __restrict__ fsB,
                        const float* __restrict__ feW, const float* __restrict__ feB,
                        const float* __restrict__ disc, const int* __restrict__ exid,
                        const float* __restrict__ kn) {
    int gt = blockIdx.x * blockDim.x + threadIdx.x;
    int w = gt >> 5, lane = gt & 31;
    if (w >= BB) return;
    int s = d_segs[w], e = d_segs[w + 1];
    const __half* __restrict__ SL = d_sumLh;
    int col = lane * 4;
    float ax = 0.f, ay = 0.f, az = 0.f, aw = 0.f;
    int t = s;
    for (; t + 4 <= e; t += 4) {
        int4 h4 = make_int4(hist[t], hist[t + 1], hist[t + 2], hist[t + 3]);
        uint2 r0 = *(const uint2*)(SL + (KD + h4.x) * KD + col);
        uint2 r1 = *(const uint2*)(SL + (KD + h4.y) * KD + col);
        uint2 r2 = *(const uint2*)(SL + (KD + h4.z) * KD + col);
        uint2 r3 = *(const uint2*)(SL + (KD + h4.w) * KD + col);
        float2 f;
        f = __half22float2(*(__half2*)&r0.x); ax += f.x; ay += f.y;
        f = __half22float2(*(__half2*)&r0.y); az += f.x; aw += f.y;
        f = __half22float2(*(__half2*)&r1.x); ax += f.x; ay += f.y;
        f = __half22float2(*(__half2*)&r1.y); az += f.x; aw += f.y;
        f = __half22float2(*(__half2*)&r2.x); ax += f.x; ay += f.y;
        f = __half22float2(*(__half2*)&r2.y); az += f.x; aw += f.y;
        f = __half22float2(*(__half2*)&r3.x); ax += f.x; ay += f.y;
        f = __half22float2(*(__half2*)&r3.y); az += f.x; aw += f.y;
    }
    for (; t < e; t++) {
        int h = hist[t];
        uint2 r = *(const uint2*)(SL + (KD + h) * KD + col);
        float2 f;
        f = __half22float2(*(__half2*)&r.x); ax += f.x; ay += f.y;
        f = __half22float2(*(__half2*)&r.y); az += f.x; aw += f.y;
    }
    float inv = 0.5f / fmaxf((float)(e - s), 1.f);
    float4 sv = make_float4(ax * inv, ay * inv, az * inv, aw * inv);

    int eid = exid[w];
    float4 ev = ((const float4*)d_sumA)[(KD + eid) * 32 + lane];
    float4 wa = ((const float4*)fsW)[lane];
    float4 wb = ((const float4*)feW)[lane];
    float ps = sv.x * wa.x + sv.y * wa.y + sv.z * wa.z + sv.w * wa.w;
    float pe = (ev.x * wb.x + ev.y * wb.y + ev.z * wb.z + ev.w * wb.w) * 0.2f;
#pragma unroll
    for (int o = 16; o; o >>= 1) {
        ps += __shfl_xor_sync(0xffffffffu, ps, o);
        pe += __shfl_xor_sync(0xffffffffu, pe, o);
    }
    float ed = 10.f * sigm(disc[eid]);
    float4 cs = ((const float4*)d_cvec)[lane];
    float4 ce = ((const float4*)(d_cvec + KD))[lane];
    float4 kv = ((const float4*)kn)[w * 32 + lane];
    float bs = fsB[0], be = feB[0];
    float x0 = ed * (sigm(ps + cs.x + bs) - sigm(pe + ce.x + be)) * kv.x;
    float x1 = ed * (sigm(ps + cs.y + bs) - sigm(pe + ce.y + be)) * kv.y;
    float x2 = ed * (sigm(ps + cs.z + bs) - sigm(pe + ce.z + be)) * kv.z;
    float x3 = ed * (sigm(ps + cs.w + bs) - sigm(pe + ce.w + be)) * kv.w;
    __half2 h01 = __floats2half2_rn(x0, x1);
    __half2 h23 = __floats2half2_rn(x2, x3);
    uint2 hv;
    hv.x = *(unsigned*)&h01;
    hv.y = *(unsigned*)&h23;
    *(uint2*)&d_xh[w * KD + lane * 4] = hv;
}

// MLP layer 1 (tensor): x(4096x128) @ W1(128x512) -> sigmoid -> d_x1h (fp16)
__global__ void __launch_bounds__(256) k_mlp1T(const float* __restrict__ b1) {
    extern __shared__ char smem[];
    __half* Bsm = (__half*)smem;
    float* stage = (float*)smem;
    int tid = threadIdx.x, w = tid >> 5, lane = tid & 31;
    int n0 = blockIdx.y * 128;

    for (int i = tid; i < 2048; i += 256) {
        int k = i >> 4, nq = (i & 15) << 3;
        *(uint4*)&Bsm[k * 128 + nq] = *(const uint4*)&d_W1h[k * H1 + n0 + nq];
    }
    __syncthreads();

    wmma::fragment<wmma::accumulator, 16, 16, 16, float> c[8];
#pragma unroll
    for (int n = 0; n < 8; n++) wmma::fill_fragment(c[n], 0.f);

    int row0 = blockIdx.x * 128 + w * 16;
    for (int kt = 0; kt < 8; kt++) {
        wmma::fragment<wmma::matrix_a, 16, 16, 16, __half, wmma::row_major> a;
        wmma::load_matrix_sync(a, d_xh + row0 * KD + kt * 16, KD);
#pragma unroll
        for (int n = 0; n < 8; n++) {
            wmma::fragment<wmma::matrix_b, 16, 16, 16, __half, wmma::row_major> b;
            wmma::load_matrix_sync(b, Bsm + kt * 16 * 128 + n * 16, 128);
            wmma::mma_sync(c[n], a, b, c[n]);
        }
    }
    __syncthreads();

    float* st = stage + w * 2048;
#pragma unroll
    for (int n = 0; n < 8; n++)
        wmma::store_matrix_sync(st + n * 16, c[n], 128, wmma::mem_row_major);
    __syncwarp();

    int col0 = lane * 4;
    float4 bias = *(const float4*)&b1[n0 + col0];
#pragma unroll
    for (int r = 0; r < 16; r++) {
        float4 v = *(float4*)&st[r * 128 + col0];
        float y0 = sigm(v.x + bias.x);
        float y1 = sigm(v.y + bias.y);
        float y2 = sigm(v.z + bias.z);
        float y3 = sigm(v.w + bias.w);
        __half2 h01 = __floats2half2_rn(y0, y1);
        __half2 h23 = __floats2half2_rn(y2, y3);
        uint2 hv;
        hv.x = *(unsigned*)&h01;
        hv.y = *(unsigned*)&h23;
        *(uint2*)&d_x1h[(row0 + r) * H1 + n0 + col0] = hv;
    }
}

// MLP layer 2 + final dot + deg-zero tail. 64 gemm CTAs (full 224 cols) + zero CTAs.
__global__ void __launch_bounds__(128) k_mlp2T(const float* __restrict__ b2,
                                               const float* __restrict__ W3,
                                               const float* __restrict__ b3,
                                               float* __restrict__ out) {
    int bx = blockIdx.x, tid = threadIdx.x;
    if (bx >= MLP2_B) {   // deg-zero tail blocks
        int i = (bx - MLP2_B) * 128 + tid;
        if (i < GN * NN) ((int*)d_deg_s)[i] = 0;
        else if (i < 2 * GN * NN) ((int*)d_deg_d)[i - GN * NN] = 0;
        return;
    }
    extern __shared__ char smem[];
    __half* Bb = (__half*)smem;                 // 2 x 32*224 halves = 28672 B
    __half* Ab = (__half*)(smem + 28672);       // 2 x 64*AP2 halves = 10240 B
    float* stage = (float*)smem;                // 57344 B epilogue overlay
    int w = tid >> 5, lane = tid & 31;
    int row0c = bx * 64;
    int ar0 = tid >> 2, ac0 = (tid & 3) * 8;
    int ar1 = (tid + 128) >> 2;

    {   // kt = 0  (B tile: 32 rows x 224 cols = 896 uint4; 7 per thread)
#pragma unroll
        for (int q = 0; q < 7; q++) {
            int idx = tid + q * 128;
            int k = idx / 28, cq = (idx - k * 28) * 8;
            *(uint4*)&Bb[k * H2P + cq] = *(const uint4*)&d_W2h[k * H2P + cq];
        }
        *(uint4*)(Ab + ar0 * AP2 + ac0) =
            *(const uint4*)(d_x1h + (row0c + ar0) * H1 + ac0);
        *(uint4*)(Ab + ar1 * AP2 + ac0) =
            *(const uint4*)(d_x1h + (row0c + ar1) * H1 + ac0);
    }
    __syncthreads();

    wmma::fragment<wmma::accumulator, 16, 16, 16, float> c[14];
#pragma unroll
    for (int n = 0; n < 14; n++) wmma::fill_fragment(c[n], 0.f);

    for (int kt = 0; kt < 16; kt++) {
        int cur = kt & 1;
        uint4 bn[7], an0, an1;
        if (kt < 15) {
            int kb = (kt + 1) * 32;
#pragma unroll
            for (int q = 0; q < 7; q++) {
                int idx = tid + q * 128;
                int k = idx / 28, cq = (idx - k * 28) * 8;
                bn[q] = *(const uint4*)&d_W2h[(kb + k) * H2P + cq];
            }
            an0 = *(const uint4*)(d_x1h + (row0c + ar0) * H1 + kb + ac0);
            an1 = *(const uint4*)(d_x1h + (row0c + ar1) * H1 + kb + ac0);
        }
#pragma unroll
        for (int kk = 0; kk < 2; kk++) {
            wmma::fragment<wmma::matrix_a, 16, 16, 16, __half, wmma::row_major> a;
            wmma::load_matrix_sync(a, Ab + cur * 64 * AP2 + (w * 16) * AP2 + kk * 16, AP2);
#pragma unroll
            for (int n = 0; n < 14; n++) {
                wmma::fragment<wmma::matrix_b, 16, 16, 16, __half, wmma::row_major> b;
                wmma::load_matrix_sync(b, Bb + cur * 7168 + kk * 16 * H2P + n * 16, H2P);
                wmma::mma_sync(c[n], a, b, c[n]);
            }
        }
        if (kt < 15) {
            int nb = cur ^ 1;
#pragma unroll
            for (int q = 0; q < 7; q++) {
                int idx = tid + q * 128;
                int k = idx / 28, cq = (idx - k * 28) * 8;
                *(uint4*)&Bb[nb * 7168 + k * H2P + cq] = bn[q];
            }
            *(uint4*)(Ab + nb * 64 * AP2 + ar0 * AP2 + ac0) = an0;
            *(uint4*)(Ab + nb * 64 * AP2 + ar1 * AP2 + ac0) = an1;
        }
        __syncthreads();
    }

    float* st = stage + w * (16 * H2P);
#pragma unroll
    for (int n = 0; n < 14; n++)
        wmma::store_matrix_sync(st + n * 16, c[n], H2P, wmma::mem_row_major);
    __syncwarp();

    // final: out[row] = sigm( sum_col sigm(st+b2) * W3 + b3 ),  cols 0..215
    float w3v[7], b2v[7];
#pragma unroll
    for (int j = 0; j < 7; j++) {
        int col = lane + 32 * j;
        bool ok = col < H2;
        w3v[j] = ok ? W3[col] : 0.f;
        b2v[j] = ok ? b2[col] : 0.f;
    }
    float bb3 = b3[0];
    int row0 = row0c + w * 16;
#pragma unroll
    for (int r = 0; r < 16; r++) {
        float s = 0.f;
#pragma unroll
        for (int j = 0; j < 7; j++) {
            int col = lane + 32 * j;
            s += sigm(st[r * H2P + col] + b2v[j]) * w3v[j];
        }
#pragma unroll
        for (int o = 16; o; o >>= 1) s += __shfl_xor_sync(0xffffffffu, s, o);
        if (lane == 0) out[row0 + r] = sigm(s + bb3);
    }
}

// ---------------- launch ----------------
extern "C" void kernel_launch(void* const* d_in, const int* in_sizes, int n_in,
                              void* d_out, int out_size) {
    const float* ent  = (const float*)d_in[0];
    const float* gcnW = (const float*)d_in[1];
    const float* gcnB = (const float*)d_in[2];
    const float* fsW  = (const float*)d_in[3];
    const float* fsB  = (const float*)d_in[4];
    const float* feW  = (const float*)d_in[5];
    const float* feB  = (const float*)d_in[6];
    const float* disc = (const float*)d_in[7];
    const float* W1   = (const float*)d_in[8];
    const float* b1   = (const float*)d_in[9];
    const float* W2   = (const float*)d_in[10];
    const float* b2   = (const float*)d_in[11];
    const float* W3   = (const float*)d_in[12];
    const float* b3   = (const float*)d_in[13];
    const int* ss = (const int*)d_in[14];
    const int* sd = (const int*)d_in[15];
    const int* ps = (const int*)d_in[16];
    const int* pd = (const int*)d_in[17];
    const int* es = (const int*)d_in[18];
    const int* ed = (const int*)d_in[19];
    const int* exid = (const int*)d_in[21];
    const float* kn  = (const float*)d_in[22];
    const int* hid   = (const int*)d_in[23];
    const int* hseg  = (const int*)d_in[24];
    float* out = (float*)d_out;

    cudaFuncSetAttribute(k_gemmT, cudaFuncAttributeMaxDynamicSharedMemorySize, 32768);
    cudaFuncSetAttribute(k_mlp1T, cudaFuncAttributeMaxDynamicSharedMemorySize, 65536);
    cudaFuncSetAttribute(k_mlp2T, cudaFuncAttributeMaxDynamicSharedMemorySize, 57344);

    k_setup<<<DEG_B + INIT_B + WCONV_B + SEG_B, 256>>>(ss, sd, ps, pd, es, ed,
                                                       ent, gcnW, gcnB, W1, W2, hseg);
    k_scan<<<GN, 1024>>>();
    k_fill<<<(GN * (EE / 16) + 255) / 256, 256>>>(ss, sd, ps, pd, es, ed);

    for (int l = 0; l < 4; l++) {
        k_agg<<<AGG_CTAS, 256>>>(l);
        k_gemmT<<<NN / 64, 128, 32768>>>(l);
    }

    k_head1<<<32, 256>>>(fsW, feW);
    k_head2<<<(BB * 32) / 256, 256>>>(hid, fsW, fsB, feW, feB, disc, exid, kn);

    dim3 g1(BB / 128, H1 / 128);
    k_mlp1T<<<g1, 256, 65536>>>(b1);
    k_mlp2T<<<MLP2_B + ZERO_B, 128, 57344>>>(b2, W3, b3, out);
}

// round 16
// speedup vs baseline: 1.0718x; 1.0718x over previous
#include <cuda_runtime.h>
#include <cuda_fp16.h>
#include <cuda_fp8.h>
#include <mma.h>

using namespace nvcuda;

#define GN 3
constexpr int NN = 16512;     // K + EXER entities  (= 129 * 128 exactly)
constexpr int KD = 128;       // embedding dim
constexpr int EE = 400000;    // edges per graph (divisible by 16)
constexpr int BB = 4096;      // batch
constexpr int TT = 204800;    // history length
constexpr int H1 = 512;
constexpr int H2 = 216;
constexpr int H2P = 224;      // padded to 14*16
constexpr int N2  = 112;      // mlp2 per-CTA col half
constexpr int CSRN = 680000;  // per-graph CSR capacity (rows padded to mult of 16)
constexpr int AP2 = 40;       // A-tile smem row pitch (halves), BK=32

// block partitioning of the fused setup kernel
constexpr int DEG_B  = (GN * (EE / 8) + 255) / 256;            // 586
constexpr int INIT_B = (NN * KD / 4) / 256;                    // 2064
constexpr int WCONV_N = GN * 4 * KD * KD + KD * H1 + H1 * H2P + 4 * KD;
constexpr int WCONV_B = (WCONV_N + 255) / 256;                 // 1474
constexpr int SEG_B  = (BB + 1 + 255) / 256;                   // 17
// k_out fused tail
constexpr int OUT_B  = (BB * 32) / 256;                        // 512
constexpr int ZERO_B = (2 * GN * NN + 255) / 256;              // 388

// ---------------- scratch (static device globals; no allocation) ----------------
__device__ int            d_deg_s[GN][NN];
__device__ int            d_deg_d[GN][NN];
__device__ int            d_rowp[GN][NN];    // 16-aligned row starts
__device__ int            d_rowe[GN][NN];    // true row ends (start + degree)
__device__ int            d_cur[GN][NN];
__device__ unsigned       d_csr4[GN][CSRN];  // src:16 | fp16 rsqrt(deg_s[src]):16 ; pad=0
__device__ unsigned char  d_h8a[NN * KD];    // fp8 e4m3 activations (gather source)
__device__ unsigned char  d_h8b[NN * KD];
__device__ __half         d_aggh[GN][NN * KD];   // fp16 aggregation (A for tensor GEMM)
__device__ __half         d_Wh[GN * 4 * KD * KD];// fp16 GCN weights [g][l][k][n]
__device__ float          d_biasC[4][KD];        // per-layer combined bias (sum over g)
__device__ __half         d_W1h[KD * H1];
__device__ __half         d_W2h[H1 * H2P];       // zero-padded cols
__device__ float          d_sumA[NN * KD];  // entity_emb + h1+h2+h3+h4  (full = /5)
__device__ float          d_sumL[NN * KD];  // h3 (written by layer-2 gemm; no init)
__device__ __half         d_sumLh[NN * KD]; // h3 + h4 fp16 (disc_full*2) for head2
__device__ int            d_segs[BB + 1];
__device__ float          d_cvec[2 * KD];
__device__ __half         d_xh[BB * KD];
__device__ __half         d_x1h[BB * H1];
__device__ float          d_x2[BB * H2];

__device__ __forceinline__ float sigm(float x) { return 1.f / (1.f + __expf(-x)); }

// ------- fused setup: degree atomics | init | weight conv | segstart ----------
__global__ void k_setup(const int* __restrict__ s0, const int* __restrict__ d0,
                        const int* __restrict__ s1, const int* __restrict__ d1,
                        const int* __restrict__ s2, const int* __restrict__ d2,
                        const float* __restrict__ ent,
                        const float* __restrict__ gcnW, const float* __restrict__ gcnB,
                        const float* __restrict__ W1, const float* __restrict__ W2,
                        const int* __restrict__ hseg) {
    int b = blockIdx.x, tid = threadIdx.x;
    if (b < DEG_B) {
        int i = b * 256 + tid;
        const int Q = EE / 8;
        if (i >= GN * Q) return;
        int g = i / Q, e8 = (i - g * Q) * 8;
        const int* S = (g == 0) ? s0 : (g == 1) ? s1 : s2;
        const int* D = (g == 0) ? d0 : (g == 1) ? d1 : d2;
        int4 sa = *(const int4*)&S[e8];
        int4 sb = *(const int4*)&S[e8 + 4];
        int4 da = *(const int4*)&D[e8];
        int4 db = *(const int4*)&D[e8 + 4];
        atomicAdd(&d_deg_s[g][sa.x], 1); atomicAdd(&d_deg_s[g][sa.y], 1);
        atomicAdd(&d_deg_s[g][sa.z], 1); atomicAdd(&d_deg_s[g][sa.w], 1);
        atomicAdd(&d_deg_s[g][sb.x], 1); atomicAdd(&d_deg_s[g][sb.y], 1);
        atomicAdd(&d_deg_s[g][sb.z], 1); atomicAdd(&d_deg_s[g][sb.w], 1);
        atomicAdd(&d_deg_d[g][da.x], 1); atomicAdd(&d_deg_d[g][da.y], 1);
        atomicAdd(&d_deg_d[g][da.z], 1); atomicAdd(&d_deg_d[g][da.w], 1);
        atomicAdd(&d_deg_d[g][db.x], 1); atomicAdd(&d_deg_d[g][db.y], 1);
        atomicAdd(&d_deg_d[g][db.z], 1); atomicAdd(&d_deg_d[g][db.w], 1);
    } else if (b < DEG_B + INIT_B) {
        int i = (b - DEG_B) * 256 + tid;
        float4 v = ((const float4*)ent)[i];
        ((float4*)d_sumA)[i] = v;
        __nv_fp8x2_storage_t lo =
            __nv_cvt_float2_to_fp8x2(make_float2(v.x, v.y), __NV_SATFINITE, __NV_E4M3);
        __nv_fp8x2_storage_t hi =
            __nv_cvt_float2_to_fp8x2(make_float2(v.z, v.w), __NV_SATFINITE, __NV_E4M3);
        ((unsigned*)d_h8a)[i] = (unsigned)lo | ((unsigned)hi << 16);
    } else if (b < DEG_B + INIT_B + WCONV_B) {
        int i = (b - DEG_B - INIT_B) * 256 + tid;
        const int A = GN * 4 * KD * KD;
        const int B = A + KD * H1;
        const int C = B + H1 * H2P;
        const int D = C + 4 * KD;
        if (i < A) {
            d_Wh[i] = __float2half_rn(gcnW[i]);
        } else if (i < B) {
            int j = i - A;
            d_W1h[j] = __float2half_rn(W1[j]);
        } else if (i < C) {
            int j = i - B;
            int k = j / H2P, n = j - k * H2P;
            d_W2h[j] = __float2half_rn(n < H2 ? W2[k * H2 + n] : 0.f);
        } else if (i < D) {
            int j = i - C;
            int l = j >> 7, col = j & 127;
            d_biasC[l][col] = gcnB[l * KD + col] + gcnB[4 * KD + l * KD + col]
                            + gcnB[8 * KD + l * KD + col];
        }
    } else {
        int i = (b - DEG_B - INIT_B - WCONV_B) * 256 + tid;
        if (i > BB) return;
        int lo = 0, hi = TT;
        while (lo < hi) { int m = (lo + hi) >> 1; if (hseg[m] < i) lo = m + 1; else hi = m; }
        d_segs[i] = lo;
    }
}

// exclusive scan of 16-ALIGNED in-degree -> row starts + true ends.
__global__ void k_scan() {
    __shared__ int sA[1024], sB[1024];
    int g = blockIdx.x, t = threadIdx.x;
    const int CH = (NN + 1023) / 1024;   // 17
    int base = t * CH;
    int s = 0;
    for (int i = 0; i < CH; i++) {
        int idx = base + i;
        if (idx < NN) s += (d_deg_d[g][idx] + 15) & ~15;
    }
    sA[t] = s;
    __syncthreads();
    int* a = sA; int* b = sB;
    for (int off = 1; off < 1024; off <<= 1) {
        b[t] = a[t] + ((t >= off) ? a[t - off] : 0);
        __syncthreads();
        int* tmp = a; a = b; b = tmp;
    }
    int incl = a[t];
    int run = incl - s;
    for (int i = 0; i < CH; i++) {
        int idx = base + i;
        if (idx < NN) {
            int deg = d_deg_d[g][idx];
            d_rowp[g][idx] = run;
            d_rowe[g][idx] = run + deg;
            d_cur[g][idx] = run;
            run += (deg + 15) & ~15;
        }
    }
}

// 16 edges per thread: deg_s gather + atomic cursor + 4-byte scatter
__global__ void k_fill(const int* __restrict__ s0, const int* __restrict__ d0,
                       const int* __restrict__ s1, const int* __restrict__ d1,
                       const int* __restrict__ s2, const int* __restrict__ d2) {
    int i = blockIdx.x * blockDim.x + threadIdx.x;
    const int Q = EE / 16;
    if (i >= GN * Q) return;
    int g = i / Q, e16 = (i - g * Q) * 16;
    const int* S = (g == 0) ? s0 : (g == 1) ? s1 : s2;
    const int* D = (g == 0) ? d0 : (g == 1) ? d1 : d2;
    int sv[16], dv[16];
#pragma unroll
    for (int q = 0; q < 4; q++) {
        *(int4*)&sv[q * 4] = *(const int4*)&S[e16 + q * 4];
        *(int4*)&dv[q * 4] = *(const int4*)&D[e16 + q * 4];
    }
    int ds[16];
#pragma unroll
    for (int q = 0; q < 16; q++) ds[q] = d_deg_s[g][sv[q]];
    int pos[16];
#pragma unroll
    for (int q = 0; q < 16; q++) pos[q] = atomicAdd(&d_cur[g][dv[q]], 1);
#pragma unroll
    for (int q = 0; q < 16; q++) {
        unsigned hb = (unsigned)__half_as_ushort(
            __float2half_rn(rsqrtf((float)max(ds[q], 1))));
        d_csr4[g][pos[q]] = (unsigned)sv[q] | (hb << 16);
    }
}

// ---------------- GCN aggregation: warp per (g, dst-row), fp8 rows ------------
// 16-aligned rows, guard-free, exact grid (R14 shape — measured local optimum).
__global__ void __launch_bounds__(256) k_agg(int layer) {
    int gt = blockIdx.x * blockDim.x + threadIdx.x;
    int w = gt >> 5, lane = gt & 31;
    int g = w / NN, n = w - g * NN;
    const unsigned char* __restrict__ hin = (layer & 1) ? d_h8b : d_h8a;
    int e0 = d_rowp[g][n], ee = d_rowe[g][n];
    int deg = ee - e0;
    int e1a = e0 + ((deg + 15) & ~15);
    const unsigned* __restrict__ cs = d_csr4[g];
    int grp = lane >> 3, sub = lane & 7;
    const unsigned char* __restrict__ hcol = hin + sub * 16;
    __half2 acc[8];
#pragma unroll
    for (int j = 0; j < 8; j++) acc[j] = __floats2half2_rn(0.f, 0.f);

    for (int base = e0; base < e1a; base += 16) {
        uint4 rr = *(const uint4*)&cs[base + 4 * grp];
        unsigned r[4] = {rr.x, rr.y, rr.z, rr.w};
        uint4 v[4];
#pragma unroll
        for (int q = 0; q < 4; q++)
            v[q] = *(const uint4*)(hcol + (int)(r[q] & 0xFFFFu) * KD);
#pragma unroll
        for (int q = 0; q < 4; q++) {
            unsigned wd = __byte_perm(r[q], r[q], 0x3232);  // {w,w} fp16x2
            __half2 w2 = *(__half2*)&wd;
            const unsigned* p = &v[q].x;
#pragma unroll
            for (int t = 0; t < 4; t++) {
                unsigned word = p[t];
                __half2_raw hlo = __nv_cvt_fp8x2_to_halfraw2(
                    (__nv_fp8x2_storage_t)(word & 0xFFFFu), __NV_E4M3);
                __half2_raw hhi = __nv_cvt_fp8x2_to_halfraw2(
                    (__nv_fp8x2_storage_t)(word >> 16), __NV_E4M3);
                acc[2 * t]     = __hfma2(w2, *(__half2*)&hlo, acc[2 * t]);
                acc[2 * t + 1] = __hfma2(w2, *(__half2*)&hhi, acc[2 * t + 1]);
            }
        }
    }
#pragma unroll
    for (int j = 0; j < 8; j++) {
        unsigned u = *(unsigned*)&acc[j];
        unsigned vv = __shfl_xor_sync(0xffffffffu, u, 8);
        __half2 t = __hadd2(acc[j], *(__half2*)&vv);
        unsigned u2 = *(unsigned*)&t;
        unsigned v2 = __shfl_xor_sync(0xffffffffu, u2, 16);
        acc[j] = __hadd2(t, *(__half2*)&v2);
    }
    if (grp == 0) {
        float rsd = rsqrtf((float)max(deg, 1));
        uint4 o0, o1;
        unsigned* oo = &o0.x;
#pragma unroll
        for (int j = 0; j < 8; j++) {
            float2 f = __half22float2(acc[j]);
            __half2 h = __floats2half2_rn(f.x * rsd, f.y * rsd);
            if (j == 4) oo = &o1.x;
            oo[j & 3] = *(unsigned*)&h;
        }
        __half* dst = &d_aggh[g][n * KD + sub * 16];
        *(uint4*)dst = o0;
        *(uint4*)(dst + 8) = o1;
    }
}

// ---------------- GCN GEMM: 64-row tiles, 128 thr, BK=32, double-buffered -----
__global__ void __launch_bounds__(128) k_gemmT(int layer) {
    extern __shared__ char smem[];
    __half* Wb = (__half*)smem;                 // 2 x 4096 halves = 16384 B
    __half* Ab = (__half*)(smem + 16384);       // 2 x 64*AP2 halves = 10240 B
    float* stage = (float*)smem;                // 32 KB epilogue overlay
    int tid = threadIdx.x, w = tid >> 5, lane = tid & 31;
    int row0c = blockIdx.x * 64;
    int ar0 = tid >> 2, ac0 = (tid & 3) * 8;
    int ar1 = (tid + 128) >> 2;

    {   // kt = 0: g=0, ks=0
        const uint4* wsrc = (const uint4*)(d_Wh + (size_t)layer * 16384);
#pragma unroll
        for (int q = 0; q < 4; q++) ((uint4*)Wb)[tid + q * 128] = wsrc[tid + q * 128];
        *(uint4*)(Ab + ar0 * AP2 + ac0) =
            *(const uint4*)(d_aggh[0] + (row0c + ar0) * KD + ac0);
        *(uint4*)(Ab + ar1 * AP2 + ac0) =
            *(const uint4*)(d_aggh[0] + (row0c + ar1) * KD + ac0);
    }
    __syncthreads();

    wmma::fragment<wmma::accumulator, 16, 16, 16, float> c[8];
#pragma unroll
    for (int n = 0; n < 8; n++) wmma::fill_fragment(c[n], 0.f);

    for (int kt = 0; kt < 12; kt++) {
        int cur = kt & 1;
        uint4 wn[4], an0, an1;
        if (kt < 11) {
            int k1 = kt + 1, g1 = k1 >> 2, ks1 = (k1 & 3) * 32;
            const uint4* wsrc = (const uint4*)(d_Wh + (size_t)(g1 * 4 + layer) * 16384
                                               + ks1 * 128);
#pragma unroll
            for (int q = 0; q < 4; q++) wn[q] = wsrc[tid + q * 128];
            an0 = *(const uint4*)(d_aggh[g1] + (row0c + ar0) * KD + ks1 + ac0);
            an1 = *(const uint4*)(d_aggh[g1] + (row0c + ar1) * KD + ks1 + ac0);
        }
#pragma unroll
        for (int kk = 0; kk < 2; kk++) {
            wmma::fragment<wmma::matrix_a, 16, 16, 16, __half, wmma::row_major> a;
            wmma::load_matrix_sync(a, Ab + cur * 64 * AP2 + (w * 16) * AP2 + kk * 16, AP2);
#pragma unroll
            for (int n = 0; n < 8; n++) {
                wmma::fragment<wmma::matrix_b, 16, 16, 16, __half, wmma::row_major> b;
                wmma::load_matrix_sync(b, Wb + cur * 4096 + kk * 16 * 128 + n * 16, 128);
                wmma::mma_sync(c[n], a, b, c[n]);
            }
        }
        if (kt < 11) {
            int nb = cur ^ 1;
#pragma unroll
            for (int q = 0; q < 4; q++) ((uint4*)(Wb + nb * 4096))[tid + q * 128] = wn[q];
            *(uint4*)(Ab + nb * 64 * AP2 + ar0 * AP2 + ac0) = an0;
            *(uint4*)(Ab + nb * 64 * AP2 + ar1 * AP2 + ac0) = an1;
        }
        __syncthreads();
    }

    float* st = stage + w * 2048;
#pragma unroll
    for (int n = 0; n < 8; n++)
        wmma::store_matrix_sync(st + n * 16, c[n], 128, wmma::mem_row_major);
    __syncwarp();

    int col0 = lane * 4;
    float4 bias = *(const float4*)&d_biasC[layer][col0];
    unsigned char* hout = (layer & 1) ? d_h8a : d_h8b;
    int row0 = row0c + w * 16;
#pragma unroll
    for (int r = 0; r < 16; r++) {
        float4 v = *(float4*)&st[r * 128 + col0];
        v.x += bias.x; v.y += bias.y; v.z += bias.z; v.w += bias.w;
        int base = (row0 + r) * KD + col0;
        __nv_fp8x2_storage_t lo =
            __nv_cvt_float2_to_fp8x2(make_float2(v.x, v.y), __NV_SATFINITE, __NV_E4M3);
        __nv_fp8x2_storage_t hi =
            __nv_cvt_float2_to_fp8x2(make_float2(v.z, v.w), __NV_SATFINITE, __NV_E4M3);
        *(unsigned*)&hout[base] = (unsigned)lo | ((unsigned)hi << 16);
        float4 sa = *(float4*)&d_sumA[base];
        sa.x += v.x; sa.y += v.y; sa.z += v.z; sa.w += v.w;
        *(float4*)&d_sumA[base] = sa;
        if (layer == 2) {
            *(float4*)&d_sumL[base] = v;
        } else if (layer == 3) {
            float4 sl = *(float4*)&d_sumL[base];
            __half2 s01 = __floats2half2_rn(sl.x + v.x, sl.y + v.y);
            __half2 s23 = __floats2half2_rn(sl.z + v.z, sl.w + v.w);
            uint2 sv2;
            sv2.x = *(unsigned*)&s01;
            sv2.y = *(unsigned*)&s23;
            *(uint2*)&d_sumLh[base] = sv2;
        }
    }
}

// ---------------- head ----------------
// cvec: warp per dot product (256 warps)
__global__ void k_head1(const float* __restrict__ stuW, const float* __restrict__ exeW) {
    int wix = blockIdx.x * 8 + (threadIdx.x >> 5);
    int lanei = threadIdx.x & 31;
    int j = wix & 127;
    bool isE = wix >= 128;
    const float* wv = isE ? (exeW + KD) : (stuW + KD);
    float s = 0.f;
    for (int k = lanei; k < KD; k += 32) s += d_sumA[j * KD + k] * wv[k];
#pragma unroll
    for (int o = 16; o; o >>= 1) s += __shfl_xor_sync(0xffffffffu, s, o);
    if (lanei == 0) d_cvec[(isE ? KD : 0) + j] = s * 0.2f;
}

// fused stu-mean + x computation: warp per batch element
__global__ void k_head2(const int* __restrict__ hist,
                        const float* __restrict__ fsW, const float* __restrict__ fsB,
                        const float* __restrict__ feW, const float* __restrict__ feB,
                        const float* __restrict__ disc, const int* __restrict__ exid,
                        const float* __restrict__ kn) {
    int gt = blockIdx.x * blockDim.x + threadIdx.x;
    int w = gt >> 5, lane = gt & 31;
    if (w >= BB) return;
    int s = d_segs[w], e = d_segs[w + 1];
    const __half* __restrict__ SL = d_sumLh;
    int col = lane * 4;
    float ax = 0.f, ay = 0.f, az = 0.f, aw = 0.f;
    int t = s;
    for (; t + 4 <= e; t += 4) {
        int4 h4 = make_int4(hist[t], hist[t + 1], hist[t + 2], hist[t + 3]);
        uint2 r0 = *(const uint2*)(SL + (KD + h4.x) * KD + col);
        uint2 r1 = *(const uint2*)(SL + (KD + h4.y) * KD + col);
        uint2 r2 = *(const uint2*)(SL + (KD + h4.z) * KD + col);
        uint2 r3 = *(const uint2*)(SL + (KD + h4.w) * KD + col);
        float2 f;
        f = __half22float2(*(__half2*)&r0.x); ax += f.x; ay += f.y;
        f = __half22float2(*(__half2*)&r0.y); az += f.x; aw += f.y;
        f = __half22float2(*(__half2*)&r1.x); ax += f.x; ay += f.y;
        f = __half22float2(*(__half2*)&r1.y); az += f.x; aw += f.y;
        f = __half22float2(*(__half2*)&r2.x); ax += f.x; ay += f.y;
        f = __half22float2(*(__half2*)&r2.y); az += f.x; aw += f.y;
        f = __half22float2(*(__half2*)&r3.x); ax += f.x; ay += f.y;
        f = __half22float2(*(__half2*)&r3.y); az += f.x; aw += f.y;
    }
    for (; t < e; t++) {
        int h = hist[t];
        uint2 r = *(const uint2*)(SL + (KD + h) * KD + col);
        float2 f;
        f = __half22float2(*(__half2*)&r.x); ax += f.x; ay += f.y;
        f = __half22float2(*(__half2*)&r.y); az += f.x; aw += f.y;
    }
    float inv = 0.5f / fmaxf((float)(e - s), 1.f);
    float4 sv = make_float4(ax * inv, ay * inv, az * inv, aw * inv);

    int eid = exid[w];
    float4 ev = ((const float4*)d_sumA)[(KD + eid) * 32 + lane];
    float4 wa = ((const float4*)fsW)[lane];
    float4 wb = ((const float4*)feW)[lane];
    float ps = sv.x * wa.x + sv.y * wa.y + sv.z * wa.z + sv.w * wa.w;
    float pe = (ev.x * wb.x + ev.y * wb.y + ev.z * wb.z + ev.w * wb.w) * 0.2f;
#pragma unroll
    for (int o = 16; o; o >>= 1) {
        ps += __shfl_xor_sync(0xffffffffu, ps, o);
        pe += __shfl_xor_sync(0xffffffffu, pe, o);
    }
    float ed = 10.f * sigm(disc[eid]);
    float4 cs = ((const float4*)d_cvec)[lane];
    float4 ce = ((const float4*)(d_cvec + KD))[lane];
    float4 kv = ((const float4*)kn)[w * 32 + lane];
    float bs = fsB[0], be = feB[0];
    float x0 = ed * (sigm(ps + cs.x + bs) - sigm(pe + ce.x + be)) * kv.x;
    float x1 = ed * (sigm(ps + cs.y + bs) - sigm(pe + ce.y + be)) * kv.y;
    float x2 = ed * (sigm(ps + cs.z + bs) - sigm(pe + ce.z + be)) * kv.z;
    float x3 = ed * (sigm(ps + cs.w + bs) - sigm(pe + ce.w + be)) * kv.w;
    __half2 h01 = __floats2half2_rn(x0, x1);
    __half2 h23 = __floats2half2_rn(x2, x3);
    uint2 hv;
    hv.x = *(unsigned*)&h01;
    hv.y = *(unsigned*)&h23;
    *(uint2*)&d_xh[w * KD + lane * 4] = hv;
}

// MLP layer 1 (tensor): x(4096x128) @ W1(128x512) -> sigmoid -> d_x1h (fp16)
__global__ void __launch_bounds__(256) k_mlp1T(const float* __restrict__ b1) {
    extern __shared__ char smem[];
    __half* Bsm = (__half*)smem;
    float* stage = (float*)smem;
    int tid = threadIdx.x, w = tid >> 5, lane = tid & 31;
    int n0 = blockIdx.y * 128;

    for (int i = tid; i < 2048; i += 256) {
        int k = i >> 4, nq = (i & 15) << 3;
        *(uint4*)&Bsm[k * 128 + nq] = *(const uint4*)&d_W1h[k * H1 + n0 + nq];
    }
    __syncthreads();

    wmma::fragment<wmma::accumulator, 16, 16, 16, float> c[8];
#pragma unroll
    for (int n = 0; n < 8; n++) wmma::fill_fragment(c[n], 0.f);

    int row0 = blockIdx.x * 128 + w * 16;
    for (int kt = 0; kt < 8; kt++) {
        wmma::fragment<wmma::matrix_a, 16, 16, 16, __half, wmma::row_major> a;
        wmma::load_matrix_sync(a, d_xh + row0 * KD + kt * 16, KD);
#pragma unroll
        for (int n = 0; n < 8; n++) {
            wmma::fragment<wmma::matrix_b, 16, 16, 16, __half, wmma::row_major> b;
            wmma::load_matrix_sync(b, Bsm + kt * 16 * 128 + n * 16, 128);
            wmma::mma_sync(c[n], a, b, c[n]);
        }
    }
    __syncthreads();

    float* st = stage + w * 2048;
#pragma unroll
    for (int n = 0; n < 8; n++)
        wmma::store_matrix_sync(st + n * 16, c[n], 128, wmma::mem_row_major);
    __syncwarp();

    int col0 = lane * 4;
    float4 bias = *(const float4*)&b1[n0 + col0];
#pragma unroll
    for (int r = 0; r < 16; r++) {
        float4 v = *(float4*)&st[r * 128 + col0];
        float y0 = sigm(v.x + bias.x);
        float y1 = sigm(v.y + bias.y);
        float y2 = sigm(v.z + bias.z);
        float y3 = sigm(v.w + bias.w);
        __half2 h01 = __floats2half2_rn(y0, y1);
        __half2 h23 = __floats2half2_rn(y2, y3);
        uint2 hv;
        hv.x = *(unsigned*)&h01;
        hv.y = *(unsigned*)&h23;
        *(uint2*)&d_x1h[(row0 + r) * H1 + n0 + col0] = hv;
    }
}

// MLP layer 2: 64-row tiles, 128 thr, grid (64,2), BK=32 double-buffered
__global__ void __launch_bounds__(128) k_mlp2T(const float* __restrict__ b2) {
    extern __shared__ char smem[];
    __half* Bb = (__half*)smem;                 // 2 x 3584 halves = 14336 B
    __half* Ab = (__half*)(smem + 14336);       // 2 x 64*AP2 halves = 10240 B
    float* stage = (float*)smem;                // 28672 B epilogue overlay
    int tid = threadIdx.x, w = tid >> 5, lane = tid & 31;
    int row0c = blockIdx.x * 64;
    int ncol0 = blockIdx.y * N2;
    int ar0 = tid >> 2, ac0 = (tid & 3) * 8;
    int ar1 = (tid + 128) >> 2;

    {   // kt = 0
#pragma unroll
        for (int q = 0; q < 4; q++) {
            int idx = tid + q * 128;
            if (idx < 448) {
                int k = idx / 14, cq = (idx - k * 14) * 8;
                *(uint4*)&Bb[k * N2 + cq] = *(const uint4*)&d_W2h[k * H2P + ncol0 + cq];
            }
        }
        *(uint4*)(Ab + ar0 * AP2 + ac0) =
            *(const uint4*)(d_x1h + (row0c + ar0) * H1 + ac0);
        *(uint4*)(Ab + ar1 * AP2 + ac0) =
            *(const uint4*)(d_x1h + (row0c + ar1) * H1 + ac0);
    }
    __syncthreads();

    wmma::fragment<wmma::accumulator, 16, 16, 16, float> c[7];
#pragma unroll
    for (int n = 0; n < 7; n++) wmma::fill_fragment(c[n], 0.f);

    for (int kt = 0; kt < 16; kt++) {
        int cur = kt & 1;
        uint4 bn[4], an0, an1;
        if (kt < 15) {
            int kb = (kt + 1) * 32;
#pragma unroll
            for (int q = 0; q < 4; q++) {
                int idx = tid + q * 128;
                if (idx < 448) {
                    int k = idx / 14, cq = (idx - k * 14) * 8;
                    bn[q] = *(const uint4*)&d_W2h[(kb + k) * H2P + ncol0 + cq];
                }
            }
            an0 = *(const uint4*)(d_x1h + (row0c + ar0) * H1 + kb + ac0);
            an1 = *(const uint4*)(d_x1h + (row0c + ar1) * H1 + kb + ac0);
        }
#pragma unroll
        for (int kk = 0; kk < 2; kk++) {
            wmma::fragment<wmma::matrix_a, 16, 16, 16, __half, wmma::row_major> a;
            wmma::load_matrix_sync(a, Ab + cur * 64 * AP2 + (w * 16) * AP2 + kk * 16, AP2);
#pragma unroll
            for (int n = 0; n < 7; n++) {
                wmma::fragment<wmma::matrix_b, 16, 16, 16, __half, wmma::row_major> b;
                wmma::load_matrix_sync(b, Bb + cur * 3584 + kk * 16 * N2 + n * 16, N2);
                wmma::mma_sync(c[n], a, b, c[n]);
            }
        }
        if (kt < 15) {
            int nb = cur ^ 1;
#pragma unroll
            for (int q = 0; q < 4; q++) {
                int idx = tid + q * 128;
                if (idx < 448) {
                    int k = idx / 14, cq = (idx - k * 14) * 8;
                    *(uint4*)&Bb[nb * 3584 + k * N2 + cq] = bn[q];
                }
            }
            *(uint4*)(Ab + nb * 64 * AP2 + ar0 * AP2 + ac0) = an0;
            *(uint4*)(Ab + nb * 64 * AP2 + ar1 * AP2 + ac0) = an1;
        }
        __syncthreads();
    }

    float* st = stage + w * (16 * N2);
#pragma unroll
    for (int n = 0; n < 7; n++)
        wmma::store_matrix_sync(st + n * 16, c[n], N2, wmma::mem_row_major);
    __syncwarp();

    int row0 = row0c + w * 16;
#pragma unroll
    for (int j = 0; j < 4; j++) {
        int col = j * 32 + lane;
        int gcol = ncol0 + col;
        if (col < N2 && gcol < H2) {
            float bb = b2[gcol];
#pragma unroll
            for (int r = 0; r < 16; r++)
                d_x2[(row0 + r) * H2 + gcol] = sigm(st[r * N2 + col] + bb);
        }
    }
}

// output + deg-array re-zero for the next call (fused tail)
__global__ void k_outz(const float* __restrict__ W3, const float* __restrict__ b3,
                       float* __restrict__ out) {
    int b = blockIdx.x, tid = threadIdx.x;
    if (b < OUT_B) {
        int gt = b * 256 + tid;
        int w = gt >> 5, lane = gt & 31;
        if (w >= BB) return;
        float s = 0.f;
        for (int k = lane; k < H2; k += 32) s += d_x2[w * H2 + k] * W3[k];
#pragma unroll
        for (int o = 16; o; o >>= 1) s += __shfl_xor_sync(0xffffffffu, s, o);
        if (lane == 0) out[w] = sigm(s + b3[0]);
    } else {
        int i = (b - OUT_B) * 256 + tid;
        if (i < GN * NN) ((int*)d_deg_s)[i] = 0;
        else if (i < 2 * GN * NN) ((int*)d_deg_d)[i - GN * NN] = 0;
    }
}

// ---------------- launch ----------------
extern "C" void kernel_launch(void* const* d_in, const int* in_sizes, int n_in,
                              void* d_out, int out_size) {
    const float* ent  = (const float*)d_in[0];
    const float* gcnW = (const float*)d_in[1];
    const float* gcnB = (const float*)d_in[2];
    const float* fsW  = (const float*)d_in[3];
    const float* fsB  = (const float*)d_in[4];
    const float* feW  = (const float*)d_in[5];
    const float* feB  = (const float*)d_in[6];
    const float* disc = (const float*)d_in[7];
    const float* W1   = (const float*)d_in[8];
    const float* b1   = (const float*)d_in[9];
    const float* W2   = (const float*)d_in[10];
    const float* b2   = (const float*)d_in[11];
    const float* W3   = (const float*)d_in[12];
    const float* b3   = (const float*)d_in[13];
    const int* ss = (const int*)d_in[14];
    const int* sd = (const int*)d_in[15];
    const int* ps = (const int*)d_in[16];
    const int* pd = (const int*)d_in[17];
    const int* es = (const int*)d_in[18];
    const int* ed = (const int*)d_in[19];
    const int* exid = (const int*)d_in[21];
    const float* kn  = (const float*)d_in[22];
    const int* hid   = (const int*)d_in[23];
    const int* hseg  = (const int*)d_in[24];
    float* out = (float*)d_out;

    cudaFuncSetAttribute(k_gemmT, cudaFuncAttributeMaxDynamicSharedMemorySize, 32768);
    cudaFuncSetAttribute(k_mlp1T, cudaFuncAttributeMaxDynamicSharedMemorySize, 65536);
    cudaFuncSetAttribute(k_mlp2T, cudaFuncAttributeMaxDynamicSharedMemorySize, 28672);

    k_setup<<<DEG_B + INIT_B + WCONV_B + SEG_B, 256>>>(ss, sd, ps, pd, es, ed,
                                                       ent, gcnW, gcnB, W1, W2, hseg);
    k_scan<<<GN, 1024>>>();
    k_fill<<<(GN * (EE / 16) + 255) / 256, 256>>>(ss, sd, ps, pd, es, ed);

    for (int l = 0; l < 4; l++) {
        k_agg<<<(GN * NN * 32) / 256, 256>>>(l);
        k_gemmT<<<NN / 64, 128, 32768>>>(l);
    }

    k_head1<<<32, 256>>>(fsW, feW);
    k_head2<<<(BB * 32) / 256, 256>>>(hid, fsW, fsB, feW, feB, disc, exid, kn);

    dim3 g1(BB / 128, H1 / 128);
    k_mlp1T<<<g1, 256, 65536>>>(b1);
    dim3 g2(BB / 64, 2);
    k_mlp2T<<<g2, 128, 28672>>>(b2);
    k_outz<<<OUT_B + ZERO_B, 256>>>(W3, b3, out);
}